// round 10
// baseline (speedup 1.0000x reference)
#include <cuda_runtime.h>

// Problem constants (fixed shapes from reference)
#define Bn  4
#define Cn  128
#define Hn  64
#define Wn  64
#define Ln  16
#define Kn  64
#define CDn 8
#define HW  (Hn * Wn)

typedef unsigned long long u64;
typedef unsigned int u32;

// ---- packed f32x2 helpers ----
__device__ __forceinline__ u64 pack2(float x, float y) {
    u64 r; asm("mov.b64 %0, {%1, %2};" : "=l"(r) : "f"(x), "f"(y)); return r;
}
__device__ __forceinline__ void unpack2(u64 v, float& x, float& y) {
    asm("mov.b64 {%0, %1}, %2;" : "=f"(x), "=f"(y) : "l"(v));
}
__device__ __forceinline__ u64 add2(u64 a, u64 b) {
    u64 d; asm("add.rn.f32x2 %0, %1, %2;" : "=l"(d) : "l"(a), "l"(b)); return d;
}
__device__ __forceinline__ u64 fma2(u64 a, u64 b, u64 c) {
    u64 d; asm("fma.rn.f32x2 %0, %1, %2, %3;" : "=l"(d) : "l"(a), "l"(b), "l"(c)); return d;
}
__device__ __forceinline__ u64 mul2(u64 a, u64 b) {
    u64 d; asm("mul.rn.f32x2 %0, %1, %2;" : "=l"(d) : "l"(a), "l"(b)); return d;
}
// Embed a 6-bit tag in the low mantissa bits (single LOP3): (bits & ~63) | tag
__device__ __forceinline__ float embed6(float s, u32 tag) {
    return __uint_as_float((__float_as_uint(s) & 0xFFFFFFC0u) | tag);
}

// Code-pair packed expanded-form argmin with index-in-mantissa tracking.
//  score_k = z.c_k - |c_k|^2/2 ; argmax score == argmin dist (exact math).
//  Table per (l, pr): 8 u64 {c_pr[j], c_pr+32[j]} + 1 u64 {hp_pr, hp_pr+32},
//  stride 10 u64 (80B, 16B-aligned). One chain of 8 fma2 produces BOTH codes'
//  scores for one pixel; the 5 smem loads serve 2 codes x 2 pixels.
//  Tracking: scores get k-tag (63-k) embedded in low 6 mantissa bits (LOP3),
//  then plain FMNMX max-chains carry value+index together. Equal-cleared
//  ties resolve to the larger tag = smaller k = argmin's first-wins rule.
//  Guard: top-2 gap < TAU(m1) (covers the <=63-ulp packing perturbation of
//  both values + eval rounding) -> warp-uniform exact diff-form fallback
//  (validated mechanism; strict <, first-k-wins == reference).
__global__ __launch_bounds__(128) void vq_kernel(
    const float* __restrict__ z,      // (B, C, H, W)
    const float* __restrict__ codes,  // (L, K, CD)
    float* __restrict__ qout,         // (B, C, H, W) or null
    float* __restrict__ idxf,         // (B, H, W, L) as float or null
    int*   __restrict__ idxi)         // (B, H, W, L) as int or null
{
    // Negated codes (fallback + output gather): (z + (-c)) == (z - c).
    __shared__ __align__(16) float cneg[2 * Kn * CDn];   // 4 KB
    // Code-pair score table: 2 l x 32 pairs x 10 u64.
    __shared__ __align__(16) u64 tbl[2 * 32 * 10];       // 5 KB

    const int tid = threadIdx.y * 64 + threadIdx.x;
    const int l0  = blockIdx.x * 2;

    #pragma unroll
    for (int i = tid; i < 2 * Kn * CDn / 4; i += 128) {
        const float4 v = reinterpret_cast<const float4*>(codes + l0 * Kn * CDn)[i];
        reinterpret_cast<float4*>(cneg)[i] = make_float4(-v.x, -v.y, -v.z, -v.w);
    }
    // Build code-pair table: threads 0..63 each own one (l, pair) entry.
    if (tid < 64) {
        const int lsb = tid >> 5;
        const int pr  = tid & 31;
        const float* c1 = codes + (l0 + lsb) * Kn * CDn + pr * CDn;
        const float* c2 = c1 + 32 * CDn;
        u64* e = tbl + (lsb * 32 + pr) * 10;
        float h1 = 0.f, h2 = 0.f;
        #pragma unroll
        for (int j = 0; j < CDn; j++) { h1 += c1[j] * c1[j]; h2 += c2[j] * c2[j]; }
        #pragma unroll
        for (int j = 0; j < CDn; j++) e[j] = pack2(c1[j], c2[j]);
        e[8] = pack2(-0.5f * h1, -0.5f * h2);
    }
    __syncthreads();

    const int w  = threadIdx.x;
    const int ls = threadIdx.y;
    const int l  = l0 + ls;
    const int h0 = blockIdx.y * 2;
    const int b  = blockIdx.z;

    // z for 2 pixels x 8 dims, each value duplicated into both f32x2 lanes.
    u64 zd[2][8];
    {
        const float* zb = z + ((b * Cn + l * CDn) * Hn + h0) * Wn + w;
        #pragma unroll
        for (int j = 0; j < 8; j++) {
            const float v0 = zb[j * HW];
            const float v1 = zb[j * HW + Wn];
            zd[0][j] = pack2(v0, v0);
            zd[1][j] = pack2(v1, v1);
        }
    }

    const u64* __restrict__ tb = tbl + ls * 32 * 10;

    // Packed trackers: value with embedded index tag, per pixel per half.
    float m1a[2] = {-3.4e38f, -3.4e38f};   // best over k in [0,32)
    float m1b[2] = {-3.4e38f, -3.4e38f};   // best over k in [32,64)
    float m2a[2] = {-3.4e38f, -3.4e38f};
    float m2b[2] = {-3.4e38f, -3.4e38f};

    #pragma unroll 2
    for (int pr = 0; pr < 32; pr++) {
        const u64* e = tb + pr * 10;
        const ulonglong2 q0 = reinterpret_cast<const ulonglong2*>(e)[0]; // dims 0,1
        const ulonglong2 q1 = reinterpret_cast<const ulonglong2*>(e)[1]; // dims 2,3
        const ulonglong2 q2 = reinterpret_cast<const ulonglong2*>(e)[2]; // dims 4,5
        const ulonglong2 q3 = reinterpret_cast<const ulonglong2*>(e)[3]; // dims 6,7
        const u64 hp = e[8];
        const u32 ta = 63u - (u32)pr;          // tag for k = pr       (32..63)
        const u32 tbg = 31u - (u32)pr;         // tag for k = pr + 32  (0..31)
        #pragma unroll
        for (int px = 0; px < 2; px++) {
            u64 d = fma2(zd[px][0], q0.x, hp);
            d = fma2(zd[px][1], q0.y, d);
            d = fma2(zd[px][2], q1.x, d);
            d = fma2(zd[px][3], q1.y, d);
            d = fma2(zd[px][4], q2.x, d);
            d = fma2(zd[px][5], q2.y, d);
            d = fma2(zd[px][6], q3.x, d);
            d = fma2(zd[px][7], q3.y, d);
            float sa, sb; unpack2(d, sa, sb);  // sa: k=pr, sb: k=pr+32
            const float pa = embed6(sa, ta);
            const float pb = embed6(sb, tbg);
            const float o1a = m1a[px], o1b = m1b[px];
            m1a[px] = fmaxf(o1a, pa);
            m2a[px] = fmaxf(m2a[px], fminf(o1a, pa));
            m1b[px] = fmaxf(o1b, pb);
            m2b[px] = fmaxf(m2b[px], fminf(o1b, pb));
        }
    }

    int kb[2];
    bool flag = false;
    #pragma unroll
    for (int px = 0; px < 2; px++) {
        const float a = m1a[px], bb = m1b[px];
        const float m1 = fmaxf(a, bb);
        const float m2 = fmaxf(fminf(a, bb), fmaxf(m2a[px], m2b[px]));
        kb[px] = 63 - (int)(__float_as_uint(m1) & 63u);
        const float tau = 1e-4f + 4e-5f * fabsf(m1);
        flag = flag || ((m1 - m2) < tau);
    }

    // ---- Rare exact fallback (warp-uniform) ----
    if (__any_sync(0xffffffffu, flag)) {
        // Re-pack z by dim pairs for the diff form.
        u64 zq[2][4];
        #pragma unroll
        for (int px = 0; px < 2; px++) {
            #pragma unroll
            for (int i = 0; i < 4; i++) {
                float e0, e1, d0, d1;
                unpack2(zd[px][2 * i], e0, d0);      // duplicated: e0 == d0
                unpack2(zd[px][2 * i + 1], e1, d1);
                zq[px][i] = pack2(e0, e1);
            }
        }
        const float4* __restrict__ cb =
            reinterpret_cast<const float4*>(cneg + ls * Kn * CDn);
        float best[2] = {3.4e38f, 3.4e38f};
        int   bi[2]   = {0, 0};
        for (int k = 0; k < Kn; k++) {
            const float4 a = cb[2 * k];
            const float4 c = cb[2 * k + 1];
            const u64 c0 = pack2(a.x, a.y);
            const u64 c1 = pack2(a.z, a.w);
            const u64 c2 = pack2(c.x, c.y);
            const u64 c3 = pack2(c.z, c.w);
            #pragma unroll
            for (int px = 0; px < 2; px++) {
                u64 d, s;
                s = add2(zq[px][0], c0); d = mul2(s, s);
                s = add2(zq[px][1], c1); d = fma2(s, s, d);
                s = add2(zq[px][2], c2); d = fma2(s, s, d);
                s = add2(zq[px][3], c3); d = fma2(s, s, d);
                float dx, dy; unpack2(d, dx, dy);
                const float dist = dx + dy;
                const float bo = best[px];
                best[px] = fminf(bo, dist);
                bi[px]   = (dist < bo) ? k : bi[px];   // strict <: first wins
            }
        }
        kb[0] = bi[0];
        kb[1] = bi[1];
    }

    // ---- Outputs ----
    const float4* __restrict__ cb4 =
        reinterpret_cast<const float4*>(cneg + ls * Kn * CDn);
    #pragma unroll
    for (int px = 0; px < 2; px++) {
        const int kp = kb[px];
        const int h  = h0 + px;
        if (qout) {
            const float4 q0 = cb4[2 * kp];
            const float4 q1 = cb4[2 * kp + 1];
            float* qb = qout + ((b * Cn + l * CDn) * Hn + h) * Wn + w;
            qb[0 * HW] = -q0.x;
            qb[1 * HW] = -q0.y;
            qb[2 * HW] = -q0.z;
            qb[3 * HW] = -q0.w;
            qb[4 * HW] = -q1.x;
            qb[5 * HW] = -q1.y;
            qb[6 * HW] = -q1.z;
            qb[7 * HW] = -q1.w;
        }
        const long long io = (((long long)b * Hn + h) * Wn + w) * Ln + l;
        if (idxf) idxf[io] = (float)kp;
        if (idxi) idxi[io] = kp;
    }
}

extern "C" void kernel_launch(void* const* d_in, const int* in_sizes, int n_in,
                              void* d_out, int out_size)
{
    const float* z     = (const float*)d_in[0];
    const float* codes = (const float*)d_in[1];
    // Defensive: if input order is (codes, z), swap by element count.
    if (n_in >= 2 && in_sizes[0] == Ln * Kn * CDn && in_sizes[1] == Bn * Cn * Hn * Wn) {
        codes = (const float*)d_in[0];
        z     = (const float*)d_in[1];
    }

    const int NQ = Bn * Cn * Hn * Wn;  // 2097152
    const int NI = Bn * Hn * Wn * Ln;  // 262144

    float* qout = nullptr;
    float* idxf = nullptr;
    int*   idxi = nullptr;

    if (out_size >= NQ + NI) {           // both outputs, flattened, float dtype
        qout = (float*)d_out;
        idxf = (float*)d_out + NQ;
    } else if (out_size == NI) {         // idx only -> int dtype
        idxi = (int*)d_out;
    } else {                             // quantized only
        qout = (float*)d_out;
    }

    dim3 grid(Ln / 2, Hn / 2, Bn);   // (8, 32, 4) = 1024 blocks
    dim3 block(64, 2, 1);            // 128 threads
    vq_kernel<<<grid, block>>>(z, codes, qout, idxf, idxi);
}